// round 8
// baseline (speedup 1.0000x reference)
#include <cuda_runtime.h>
#include <cuda_bf16.h>

// CenterLoss == per-row gathered squared distance:
// loss = [ sum_b clip(||x_b - c_{l_b}||^2, 1e-12, 1e12) + B*(C-1)*1e-12 ] / B
//
// Inputs: x [B, D] f32, labels [B] int32, centers [C, D] f32. Output: scalar f32.
//
// R8 = R5 memory shape (the empirical best: 512 CTAs x 256 thr, one warp per
// row, 4 x-float4 + 4 c-float4 per thread) + fence-free epilogue:
//  - slot accumulation via red.release.gpu (no __threadfence / MEMBAR.GPU)
//  - completion count via atom.acq_rel.gpu.inc (acquire pairs with releases)
//  - last CTA: 32 lanes read 32 scattered slots in parallel, butterfly, STG.

#define BATCH 4096
#define FEAT 512
#define NCLASSES 10000
#define WARPS_PER_BLOCK 8
#define NBLOCKS (BATCH / WARPS_PER_BLOCK)   // 512
#define NSLOTS 32

__device__ float g_part[NSLOTS * 32];        // every 32nd float: 128B stride
__device__ unsigned int g_count = 0;

__device__ __forceinline__ void red_add_release(float* addr, float v) {
    asm volatile("red.release.gpu.global.add.f32 [%0], %1;"
                 :: "l"(addr), "f"(v) : "memory");
}
__device__ __forceinline__ unsigned atomic_inc_acq_rel(unsigned* addr, unsigned wrap) {
    unsigned old;
    asm volatile("atom.acq_rel.gpu.global.inc.u32 %0, [%1], %2;"
                 : "=r"(old) : "l"(addr), "r"(wrap) : "memory");
    return old;
}

__global__ __launch_bounds__(256) void center_loss_kernel(
    const float* __restrict__ x,
    const int* __restrict__ labels,
    const float* __restrict__ centers,
    float* __restrict__ out)
{
    const int tid  = threadIdx.x;
    const int warp = tid >> 5;
    const int lane = tid & 31;
    const int row  = blockIdx.x * WARPS_PER_BLOCK + warp;

    // uniform broadcast label load heads the dependency chain
    int lbl = labels[row];
    lbl = min(max(lbl, 0), NCLASSES - 1);

    const float4* xr = reinterpret_cast<const float4*>(x + (size_t)row * FEAT);
    const float4* cr = reinterpret_cast<const float4*>(centers + (size_t)lbl * FEAT);

    float4 xv[4], cv[4];
#pragma unroll
    for (int i = 0; i < 4; i++) xv[i] = xr[lane + 32 * i];
#pragma unroll
    for (int i = 0; i < 4; i++) cv[i] = cr[lane + 32 * i];

    float s = 0.0f;
#pragma unroll
    for (int i = 0; i < 4; i++) {
        float d0 = xv[i].x - cv[i].x;
        float d1 = xv[i].y - cv[i].y;
        float d2 = xv[i].z - cv[i].z;
        float d3 = xv[i].w - cv[i].w;
        s += d0 * d0 + d1 * d1 + d2 * d2 + d3 * d3;
    }

#pragma unroll
    for (int off = 16; off > 0; off >>= 1)
        s += __shfl_xor_sync(0xFFFFFFFFu, s, off);

    __shared__ float warp_sums[WARPS_PER_BLOCK];
    if (lane == 0) {
        // faithful per-entry clamp of the true-class distance
        warp_sums[warp] = fminf(fmaxf(s, 1e-12f), 1e12f);
    }
    __syncthreads();

    if (warp == 0) {
        float p = (lane < WARPS_PER_BLOCK) ? warp_sums[lane] : 0.0f;
#pragma unroll
        for (int off = 4; off > 0; off >>= 1)
            p += __shfl_xor_sync(0xFFFFFFFFu, p, off);

        unsigned done = 0;
        if (lane == 0) {
            // release: makes this add visible before the count increment lands
            red_add_release(&g_part[(blockIdx.x & (NSLOTS - 1)) * 32], p);
            // acq_rel inc: wraps to 0 on the last CTA; acquire pairs with all
            // prior releases so slot values are visible below
            done = (atomic_inc_acq_rel(&g_count, NBLOCKS - 1) == NBLOCKS - 1) ? 1u : 0u;
        }
        done = __shfl_sync(0xFFFFFFFFu, done, 0);

        if (done) {
            // parallel slot gather: lane i owns slot i (independent lines)
            float t = g_part[lane * 32];
            g_part[lane * 32] = 0.0f;     // reset for next graph replay
#pragma unroll
            for (int off = 16; off > 0; off >>= 1)
                t += __shfl_xor_sync(0xFFFFFFFFu, t, off);
            if (lane == 0) {
                out[0] = t * (1.0f / (float)BATCH)
                       + (float)((double)(NCLASSES - 1) * 1e-12);
            }
        }
    }
}

extern "C" void kernel_launch(void* const* d_in, const int* in_sizes, int n_in,
                              void* d_out, int out_size) {
    const float* x = (const float*)d_in[0];
    const int* labels = (const int*)d_in[1];
    const float* centers = (const float*)d_in[2];
    float* out = (float*)d_out;

    center_loss_kernel<<<NBLOCKS, 256>>>(x, labels, centers, out);
}